// round 15
// baseline (speedup 1.0000x reference)
#include <cuda_runtime.h>
#include <cstdint>

#define BB_ 8
#define CC_ 256
#define HH_ 128
#define WW_ 128
#define NPIX (BB_*HH_*WW_)   // 131072
#define HW_ (16384)

// Bit-packed scratch. Per pixel: 8 uint32 words (= 2 uint4); bit i of word wd
// = channel wd*32+i, 1 <=> value >= 0.
__device__ uint4 g_xbits[NPIX*2];       // 4 MB  binarized input
__device__ uint4 g_mbits[NPIX*2];       // 4 MB  binarized mid (bits)
__device__ unsigned char g_mid8[(size_t)NPIX*CC_];  // 33.5 MB mid as s8 (+1/-1)
__device__ uint4 g_wb  [4*5*64*2];      // branch weights: [br][k][o][2]
__device__ uint4 g_wcb [9*256*2];       // main weights:   [t][o][2]
__device__ unsigned char g_wm8[9*256*256]; // main weights s8: [t][o][c]
__device__ int   g_pwb [4*5*64];        // branch weight popcounts
__device__ int   g_pwc [9*256];         // main weight popcounts

__device__ __forceinline__ unsigned x3(unsigned a, unsigned b, unsigned c) {
    unsigned r; asm("lop3.b32 %0, %1, %2, %3, 0x96;" : "=r"(r) : "r"(a), "r"(b), "r"(c)); return r;
}
__device__ __forceinline__ unsigned mj(unsigned a, unsigned b, unsigned c) {
    unsigned r; asm("lop3.b32 %0, %1, %2, %3, 0xE8;" : "=r"(r) : "r"(a), "r"(b), "r"(c)); return r;
}
__device__ __forceinline__ void cdot8_acc(int& acc, uint4 xa, uint4 xb, uint4 wa, uint4 wb) {
    unsigned v0 = xa.x^wa.x, v1 = xa.y^wa.y, v2 = xa.z^wa.z, v3 = xa.w^wa.w;
    unsigned v4 = xb.x^wb.x, v5 = xb.y^wb.y, v6 = xb.z^wb.z, v7 = xb.w^wb.w;
    unsigned s0 = x3(v0, v1, v2), c0 = mj(v0, v1, v2);
    unsigned s1 = x3(v3, v4, v5), c1 = mj(v3, v4, v5);
    unsigned s2 = x3(s0, s1, v6), c2 = mj(s0, s1, v6);
    unsigned s3 = x3(c0, c1, c2), c3 = mj(c0, c1, c2);
    int t1, t2;
    asm("mad.lo.s32 %0, %1, 2, %2;" : "=r"(t1) : "r"(__popc(s3)), "r"(__popc(s2)));
    asm("mad.lo.s32 %0, %1, 4, %2;" : "=r"(t2) : "r"(__popc(c3)), "r"(__popc(v7)));
    acc = acc + t1 + t2;
}

// ---- IMMA helpers (verified in R3) ----
__device__ __forceinline__ unsigned smem_u32(const void* p) {
    return (unsigned)__cvta_generic_to_shared(p);
}
__device__ __forceinline__ void cp16(unsigned s, const void* g, bool v) {
    int sz = v ? 16 : 0;
    asm volatile("cp.async.cg.shared.global [%0], [%1], 16, %2;" :: "r"(s), "l"(g), "r"(sz));
}
__device__ __forceinline__ void cp_commit() { asm volatile("cp.async.commit_group;"); }
template<int N> __device__ __forceinline__ void cp_wait() {
    asm volatile("cp.async.wait_group %0;" :: "n"(N));
}
__device__ __forceinline__ void ldsm4(unsigned &r0, unsigned &r1, unsigned &r2, unsigned &r3, unsigned a) {
    asm volatile("ldmatrix.sync.aligned.m8n8.x4.shared.b16 {%0,%1,%2,%3}, [%4];"
        : "=r"(r0), "=r"(r1), "=r"(r2), "=r"(r3) : "r"(a));
}
__device__ __forceinline__ void mma8(int* d, unsigned a0, unsigned a1, unsigned a2, unsigned a3,
                                     unsigned b0, unsigned b1) {
    asm volatile("mma.sync.aligned.m16n8k32.row.col.s32.s8.s8.s32 "
        "{%0,%1,%2,%3}, {%4,%5,%6,%7}, {%8,%9}, {%0,%1,%2,%3};"
        : "+r"(d[0]), "+r"(d[1]), "+r"(d[2]), "+r"(d[3])
        : "r"(a0), "r"(a1), "r"(a2), "r"(a3), "r"(b0), "r"(b1));
}

// ---------------------------------------------------------------------------
__global__ __launch_bounds__(256) void pack_x(const float* __restrict__ x) {
    int tid = blockIdx.x*256 + threadIdx.x;
    int wd  = tid >> 17;
    int pix = tid & (NPIX-1);
    int b   = pix >> 14;
    int hw  = pix & (HW_-1);
    const float* p = x + ((size_t)(b*CC_ + wd*32))*HW_ + hw;
    unsigned bits = 0;
    #pragma unroll
    for (int i = 0; i < 32; i++)
        if (p[(size_t)i*HW_] >= 0.f) bits |= (1u << i);
    ((unsigned*)g_xbits)[pix*8 + wd] = bits;
}

// ---------------------------------------------------------------------------
__global__ __launch_bounds__(256) void pack_w(
    const float* __restrict__ w1, const float* __restrict__ w2,
    const float* __restrict__ w3, const float* __restrict__ w4,
    const float* __restrict__ wc)
{
    int tid = blockIdx.x*256 + threadIdx.x;
    if (tid < 4*5*64*8) {
        int wd = tid & 7;
        int o  = (tid >> 3) & 63;
        int kk = tid >> 9;          // br*5 + k
        int k  = kk % 5, br = kk / 5;
        const float* src = (br==0) ? w1 : (br==1) ? w2 : (br==2) ? w3 : w4;
        unsigned bits = 0;
        #pragma unroll
        for (int i = 0; i < 32; i++) {
            int c = wd*32 + i;
            float v = src[(o*CC_ + c)*5 + k];
            if (v >= 0.f) bits |= (1u << i);
        }
        ((unsigned*)g_wb)[tid] = bits;
        int pc = __popc(bits);
        pc += __shfl_xor_sync(0xffffffffu, pc, 1);
        pc += __shfl_xor_sync(0xffffffffu, pc, 2);
        pc += __shfl_xor_sync(0xffffffffu, pc, 4);
        if (wd == 0) g_pwb[kk*64 + o] = pc;
    } else {
        int j = tid - 4*5*64*8;
        if (j < 9*256*8) {
            int wd = j & 7;
            int o  = (j >> 3) & 255;
            int t  = j >> 11;
            unsigned bits = 0;
            #pragma unroll
            for (int i = 0; i < 32; i++) {
                int c = wd*32 + i;
                float v = wc[(o*CC_ + c)*9 + t];
                if (v >= 0.f) bits |= (1u << i);
            }
            ((unsigned*)g_wcb)[j] = bits;
            // s8 copy for the tensor path
            unsigned* wdst = (unsigned*)(g_wm8 + ((size_t)(t*256 + o))*256 + wd*32);
            #pragma unroll
            for (int w = 0; w < 8; w++) {
                unsigned bw = 0;
                #pragma unroll
                for (int kq = 0; kq < 4; kq++)
                    bw |= (((bits >> (w*4 + kq)) & 1u) ? 0x01u : 0xFFu) << (kq*8);
                wdst[w] = bw;
            }
            int pc = __popc(bits);
            pc += __shfl_xor_sync(0xffffffffu, pc, 1);
            pc += __shfl_xor_sync(0xffffffffu, pc, 2);
            pc += __shfl_xor_sync(0xffffffffu, pc, 4);
            if (wd == 0) g_pwc[t*256 + o] = pc;
        }
    }
}

// ---------------------------------------------------------------------------
// Branch convs (R14 best config) + s8 mid emission for the tensor path.
__global__ __launch_bounds__(512, 2) void branch_conv(
    const float* __restrict__ b1, const float* __restrict__ b2,
    const float* __restrict__ b3, const float* __restrict__ b4,
    const float* __restrict__ a1p)
{
    __shared__ uint4 xt[9*40*2];
    const int bx = blockIdx.x, h = blockIdx.y, bb = blockIdx.z;
    const int w0 = bx*32;
    const int tid = threadIdx.x, lane = tid & 31;
    const int br = (tid >> 5) & 3, q = tid >> 7, px0 = q*8;

    for (int i = tid; i < 9*40; i += 512) {
        int r = i / 40, c = i % 40;
        int hh = h - 4 + r, ww = w0 - 4 + c;
        uint4 v0 = make_uint4(0,0,0,0), v1 = v0;
        if ((unsigned)hh < HH_ && (unsigned)ww < WW_) {
            const uint4* s = g_xbits + ((bb*HH_ + hh)*WW_ + ww)*2;
            v0 = s[0]; v1 = s[1];
        }
        xt[i*2] = v0; xt[i*2+1] = v1;
    }
    __syncthreads();

    const int sh = (br >= 2) ? ((br == 2) ? 1 : 2) : 0;
    const int sw = (br <  2) ? ((br == 0) ? 1 : 2) : 0;
    const bool edge = (br < 2) ? (bx == 0 || bx == 3) : (h < 4 || h > 123);

    int acc[16];
    #pragma unroll
    for (int p = 0; p < 16; p++) acc[p] = 0;

    #pragma unroll 1
    for (int k = 0; k < 5; k++) {
        const uint4* wpA = g_wb + ((br*5 + k)*64 + lane)*2;
        const uint4* wpB = wpA + 64;
        uint4 wA0 = wpA[0], wA1 = wpA[1];
        uint4 wB0 = wpB[0], wB1 = wpB[1];
        int d = k - 2;
        const uint4* s = xt + ((4 + d*sh)*40 + 4 + d*sw + px0)*2;
        #pragma unroll
        for (int p = 0; p < 8; p++) {
            uint4 x0 = s[2*p], x1 = s[2*p+1];
            cdot8_acc(acc[p],   x0, x1, wA0, wA1);
            cdot8_acc(acc[8+p], x0, x1, wB0, wB1);
        }
    }
    if (edge) {
        #pragma unroll 1
        for (int k = 0; k < 5; k++) {
            int pwA = 128 - g_pwb[(br*5 + k)*64 + lane];
            int pwB = 128 - g_pwb[(br*5 + k)*64 + lane + 32];
            int d = k - 2;
            bool hInv = ((unsigned)(h + d*sh) >= HH_);
            #pragma unroll
            for (int p = 0; p < 8; p++) {
                int ww = w0 + px0 + p + d*sw;
                if (hInv || (unsigned)ww >= WW_) {
                    acc[p]   += pwA;
                    acc[8+p] += pwB;
                }
            }
        }
    }

    const float* bp = (br==0) ? b1 : (br==1) ? b2 : (br==2) ? b3 : b4;
    const float biasA = bp[lane], biasB = bp[lane + 32];
    const float a1 = a1p[0];
    unsigned* mout = (unsigned*)g_mbits + ((bb*HH_ + h)*WW_ + w0 + px0)*8 + br*2;
    unsigned char* m8 = g_mid8 + ((size_t)((bb*HH_ + h)*WW_ + w0 + px0))*CC_ + br*64 + lane;
    #pragma unroll
    for (int p = 0; p < 8; p++) {
        float vA = (float)(1280 - 2*acc[p])   + biasA;
        float vB = (float)(1280 - 2*acc[8+p]) + biasB;
        float pA = (vA >= 0.f) ? vA : a1*vA;
        float pB = (vB >= 0.f) ? vB : a1*vB;
        unsigned mA = __ballot_sync(0xffffffffu, pA >= 0.f);
        unsigned mB = __ballot_sync(0xffffffffu, pB >= 0.f);
        if (lane == 0) { mout[p*8] = mA; mout[p*8 + 1] = mB; }
        m8[(size_t)p*CC_]      = (pA >= 0.f) ? 0x01 : 0xFF;
        m8[(size_t)p*CC_ + 32] = (pB >= 0.f) ? 0x01 : 0xFF;
    }
}

// ---------------------------------------------------------------------------
// Main 3x3 conv, HYBRID. 512 thr: threads 0..447 (14 warps) = popcount for
// oc 0..223 (rolling-column, R14 shape); threads 448..511 (2 warps) = s8 IMMA
// on the tensor pipe for oc 224..255. Disjoint named barriers.
__global__ __launch_bounds__(512, 2) void main_conv(
    const float* __restrict__ x, const float* __restrict__ bc,
    const float* __restrict__ a2p, float* __restrict__ out)
{
    __shared__ uint4 xt[3*34*2];                         // 3.3 KB (bits)
    __shared__ __align__(16) unsigned char aT[3*34*256]; // 26.1 KB s8 halo
    __shared__ __align__(16) unsigned char bT[2][32*256];// 16.4 KB s8 weights
    const int bx = blockIdx.x, h = blockIdx.y, bb = blockIdx.z;
    const int w0 = bx*32;
    const int tid = threadIdx.x;

    if (tid < 448) {
        // ---------------- popcount path: oc 0..223 ----------------
        const int half = tid / 224;
        const int oc   = tid - half*224;
        const int px0  = half*16;

        for (int i = tid; i < 3*34; i += 448) {
            int r = i / 34, c = i % 34;
            int hh = h - 1 + r, ww = w0 - 1 + c;
            uint4 v0 = make_uint4(0,0,0,0), v1 = v0;
            if ((unsigned)hh < HH_ && (unsigned)ww < WW_) {
                const uint4* s = g_mbits + ((bb*HH_ + hh)*WW_ + ww)*2;
                v0 = s[0]; v1 = s[1];
            }
            xt[i*2] = v0; xt[i*2+1] = v1;
        }
        asm volatile("bar.sync 0, 448;" ::: "memory");

        int acc[16];
        #pragma unroll
        for (int p = 0; p < 16; p++) acc[p] = 0;

        #pragma unroll 1
        for (int r = 0; r < 3; r++) {
            const uint4* wp0 = g_wcb + ((r*3 + 0)*256 + oc)*2;
            const uint4* wp1 = g_wcb + ((r*3 + 1)*256 + oc)*2;
            const uint4* wp2 = g_wcb + ((r*3 + 2)*256 + oc)*2;
            uint4 w00 = wp0[0], w01 = wp0[1];
            uint4 w10 = wp1[0], w11 = wp1[1];
            uint4 w20 = wp2[0], w21 = wp2[1];
            const uint4* srow = xt + (r*34 + px0)*2;
            #pragma unroll
            for (int jj = 0; jj < 18; jj++) {
                uint4 x0 = srow[2*jj], x1 = srow[2*jj+1];
                if (jj >= 2)             cdot8_acc(acc[jj-2], x0, x1, w20, w21);
                if (jj >= 1 && jj <= 16) cdot8_acc(acc[jj-1], x0, x1, w10, w11);
                if (jj <= 15)            cdot8_acc(acc[jj],   x0, x1, w00, w01);
            }
        }
        const bool edge = (h == 0) | (h == 127) | (bx == 0) | (bx == 3);
        if (edge) {
            #pragma unroll 1
            for (int t = 0; t < 9; t++) {
                int pw = 128 - g_pwc[t*256 + oc];
                bool hInv = ((unsigned)(h + t/3 - 1) >= HH_);
                int dw = t%3 - 1;
                #pragma unroll
                for (int p = 0; p < 16; p++) {
                    int ww = w0 + px0 + p + dw;
                    if (hInv || (unsigned)ww >= WW_) acc[p] += pw;
                }
            }
        }

        const float a2 = a2p[0];
        const float bias = bc[oc];
        const size_t gbase = (((size_t)bb*CC_ + oc)*HH_ + h)*WW_ + w0 + px0;
        #pragma unroll
        for (int q = 0; q < 4; q++) {
            float4 xr = *(const float4*)(x + gbase + q*4);
            float4 o4;
            float v0 = (float)(2304 - 2*acc[q*4+0]) + bias; v0 = (v0 >= 0.f) ? v0 : a2*v0;
            float v1 = (float)(2304 - 2*acc[q*4+1]) + bias; v1 = (v1 >= 0.f) ? v1 : a2*v1;
            float v2 = (float)(2304 - 2*acc[q*4+2]) + bias; v2 = (v2 >= 0.f) ? v2 : a2*v2;
            float v3 = (float)(2304 - 2*acc[q*4+3]) + bias; v3 = (v3 >= 0.f) ? v3 : a2*v3;
            o4.x = v0 + xr.x; o4.y = v1 + xr.y; o4.z = v2 + xr.z; o4.w = v3 + xr.w;
            *(float4*)(out + gbase + q*4) = o4;
        }
    } else {
        // ---------------- IMMA path: oc 224..255 ----------------
        const int l = tid - 448;          // 0..63
        const int wim = l >> 5;           // warp m-half: px [wim*16, wim*16+16)
        const int lane = l & 31;

        // A halo tile (3 rows x 34 px x 256 ch), zero-filled OOB
        for (int i = l; i < 1632; i += 64) {       // 1632 16B chunks
            int pxl = i >> 4, ch = i & 15;
            int r = pxl / 34, pc = pxl - r*34;
            int hh = h - 1 + r, ww = w0 - 1 + pc;
            bool v = ((unsigned)hh < HH_) && ((unsigned)ww < WW_);
            const unsigned char* src = g_mid8 +
                ((size_t)((bb*HH_ + (v ? hh : 0))*WW_ + (v ? ww : 0)))*CC_ + ch*16;
            cp16(smem_u32(aT + r*8704 + pc*256 + ((ch ^ (pc & 7)) << 4)), src, v);
        }
        // B tap 0 (32 ocs x 256 ch)
        for (int i = l; i < 512; i += 64) {
            int o = i >> 4, ch = i & 15;
            cp16(smem_u32(bT[0] + o*256 + ((ch ^ (o & 7)) << 4)),
                 g_wm8 + ((size_t)(224 + o))*256 + ch*16, true);
        }
        cp_commit(); cp_wait<0>();
        asm volatile("bar.sync 1, 64;" ::: "memory");

        int acc[4][4];
        #pragma unroll
        for (int i = 0; i < 4; i++)
            #pragma unroll
            for (int j = 0; j < 4; j++) acc[i][j] = 0;

        const int a_row = lane & 15;
        const int a_kx  = (lane >> 4) & 1;
        const int b_row = (lane & 7) + ((lane >> 4) & 1) * 8;
        const int b_kx  = (lane >> 3) & 1;

        for (int t = 0; t < 9; t++) {
            if (t < 8) {                  // prefetch next tap's B
                for (int i = l; i < 512; i += 64) {
                    int o = i >> 4, ch = i & 15;
                    cp16(smem_u32(bT[(t+1)&1] + o*256 + ((ch ^ (o & 7)) << 4)),
                         g_wm8 + ((size_t)((t+1)*256 + 224 + o))*256 + ch*16, true);
                }
                cp_commit();
            }
            int r = t/3, dc = t%3;
            unsigned aB = smem_u32(aT + r*8704);
            unsigned bB = smem_u32(bT[t&1]);
            int p = wim*16 + a_row + dc;  // smem col (col 0 = pixel w0-1)
            #pragma unroll
            for (int ks = 0; ks < 8; ks++) {
                unsigned a0, a1, a2q, a3;
                ldsm4(a0, a1, a2q, a3, aB + p*256 + (((2*ks + a_kx) ^ (p & 7)) << 4));
                #pragma unroll
                for (int bt = 0; bt < 2; bt++) {
                    unsigned r0, r1, r2, r3;
                    int o = bt*16 + b_row;
                    ldsm4(r0, r1, r2, r3, bB + o*256 + (((2*ks + b_kx) ^ (o & 7)) << 4));
                    mma8(acc[2*bt],     a0, a1, a2q, a3, r0, r1);
                    mma8(acc[2*bt + 1], a0, a1, a2q, a3, r2, r3);
                }
            }
            cp_wait<0>();
            asm volatile("bar.sync 1, 64;" ::: "memory");
        }

        const float a2 = a2p[0];
        #pragma unroll
        for (int nt = 0; nt < 4; nt++)
            #pragma unroll
            for (int d = 0; d < 4; d++) {
                int px  = wim*16 + (lane >> 2) + 8*(d >> 1);
                int ocl = 224 + nt*8 + (lane & 3)*2 + (d & 1);
                float v = (float)acc[nt][d] + bc[ocl];
                v = (v >= 0.f) ? v : a2*v;
                size_t gi = (((size_t)bb*CC_ + ocl)*HH_ + h)*WW_ + w0 + px;
                out[gi] = v + x[gi];
            }
    }
}

// ---------------------------------------------------------------------------
extern "C" void kernel_launch(void* const* d_in, const int* in_sizes, int n_in,
                              void* d_out, int out_size) {
    const float* x  = (const float*)d_in[0];
    const float* w1 = (const float*)d_in[1];
    const float* b1 = (const float*)d_in[2];
    const float* w2 = (const float*)d_in[3];
    const float* b2 = (const float*)d_in[4];
    const float* w3 = (const float*)d_in[5];
    const float* b3 = (const float*)d_in[6];
    const float* w4 = (const float*)d_in[7];
    const float* b4 = (const float*)d_in[8];
    const float* a1 = (const float*)d_in[9];
    const float* wc = (const float*)d_in[10];
    const float* bc = (const float*)d_in[11];
    const float* a2 = (const float*)d_in[12];
    float* out = (float*)d_out;

    pack_x<<<4096, 256>>>(x);
    pack_w<<<112, 256>>>(w1, w2, w3, w4, wc);
    branch_conv<<<dim3(4,128,8), 512>>>(b1, b2, b3, b4, a1);
    main_conv<<<dim3(4,128,8), 512>>>(x, bc, a2, out);
}

// round 16
// speedup vs baseline: 1.0731x; 1.0731x over previous
#include <cuda_runtime.h>
#include <cstdint>

#define BB_ 8
#define CC_ 256
#define HH_ 128
#define WW_ 128
#define NPIX (BB_*HH_*WW_)   // 131072
#define HW_ (16384)

// Bit-packed scratch. Per pixel: 8 uint32 words (= 2 uint4); bit i of word wd
// = channel wd*32+i, 1 <=> value >= 0.
__device__ uint4 g_xbits[NPIX*2];       // 4 MB  binarized input
__device__ uint4 g_mbits[NPIX*2];       // 4 MB  binarized mid
__device__ uint4 g_wb  [4*5*64*2];      // branch weights: [br][k][o][2]
__device__ uint4 g_wcb [9*256*2];       // main weights:   [t][o][2]
__device__ int   g_pwb [4*5*64];        // branch weight popcounts [br*5+k][o]
__device__ int   g_pwc [9*256];         // main weight popcounts   [t][o]

__device__ __forceinline__ unsigned x3(unsigned a, unsigned b, unsigned c) {
    unsigned r; asm("lop3.b32 %0, %1, %2, %3, 0x96;" : "=r"(r) : "r"(a), "r"(b), "r"(c)); return r;
}
__device__ __forceinline__ unsigned mj(unsigned a, unsigned b, unsigned c) {
    unsigned r; asm("lop3.b32 %0, %1, %2, %3, 0xE8;" : "=r"(r) : "r"(a), "r"(b), "r"(c)); return r;
}

// CSA-compressed 8-word xor-popcount accumulate (R12 combine shape):
// alu: 8 XOR + 8 LOP3 + 1 IADD3; popc: 4 POPC; fma: 2 IMAD (independent).
__device__ __forceinline__ void cdot8_acc(int& acc, uint4 xa, uint4 xb, uint4 wa, uint4 wb) {
    unsigned v0 = xa.x^wa.x, v1 = xa.y^wa.y, v2 = xa.z^wa.z, v3 = xa.w^wa.w;
    unsigned v4 = xb.x^wb.x, v5 = xb.y^wb.y, v6 = xb.z^wb.z, v7 = xb.w^wb.w;
    unsigned s0 = x3(v0, v1, v2), c0 = mj(v0, v1, v2);
    unsigned s1 = x3(v3, v4, v5), c1 = mj(v3, v4, v5);
    unsigned s2 = x3(s0, s1, v6), c2 = mj(s0, s1, v6);
    unsigned s3 = x3(c0, c1, c2), c3 = mj(c0, c1, c2);
    int t1, t2;
    asm("mad.lo.s32 %0, %1, 2, %2;" : "=r"(t1) : "r"(__popc(s3)), "r"(__popc(s2)));
    asm("mad.lo.s32 %0, %1, 4, %2;" : "=r"(t2) : "r"(__popc(c3)), "r"(__popc(v7)));
    acc = acc + t1 + t2;
}

// ---------------------------------------------------------------------------
__global__ __launch_bounds__(256) void pack_x(const float* __restrict__ x) {
    int tid = blockIdx.x*256 + threadIdx.x;
    int wd  = tid >> 17;
    int pix = tid & (NPIX-1);
    int b   = pix >> 14;
    int hw  = pix & (HW_-1);
    const float* p = x + ((size_t)(b*CC_ + wd*32))*HW_ + hw;
    unsigned bits = 0;
    #pragma unroll
    for (int i = 0; i < 32; i++)
        if (p[(size_t)i*HW_] >= 0.f) bits |= (1u << i);
    ((unsigned*)g_xbits)[pix*8 + wd] = bits;
}

// ---------------------------------------------------------------------------
// Pack weights + per-(tap,oc) popcount tables (in-warp 8-lane reduction;
// groups of 8 lanes are warp-aligned in both sections).
__global__ __launch_bounds__(256) void pack_w(
    const float* __restrict__ w1, const float* __restrict__ w2,
    const float* __restrict__ w3, const float* __restrict__ w4,
    const float* __restrict__ wc)
{
    int tid = blockIdx.x*256 + threadIdx.x;
    if (tid < 4*5*64*8) {
        int wd = tid & 7;
        int o  = (tid >> 3) & 63;
        int kk = tid >> 9;          // br*5 + k
        int k  = kk % 5, br = kk / 5;
        const float* src = (br==0) ? w1 : (br==1) ? w2 : (br==2) ? w3 : w4;
        unsigned bits = 0;
        #pragma unroll
        for (int i = 0; i < 32; i++) {
            int c = wd*32 + i;
            float v = src[(o*CC_ + c)*5 + k];
            if (v >= 0.f) bits |= (1u << i);
        }
        ((unsigned*)g_wb)[tid] = bits;
        int pc = __popc(bits);
        pc += __shfl_xor_sync(0xffffffffu, pc, 1);
        pc += __shfl_xor_sync(0xffffffffu, pc, 2);
        pc += __shfl_xor_sync(0xffffffffu, pc, 4);
        if (wd == 0) g_pwb[kk*64 + o] = pc;
    } else {
        int j = tid - 4*5*64*8;
        if (j < 9*256*8) {
            int wd = j & 7;
            int o  = (j >> 3) & 255;
            int t  = j >> 11;
            unsigned bits = 0;
            #pragma unroll
            for (int i = 0; i < 32; i++) {
                int c = wd*32 + i;
                float v = wc[(o*CC_ + c)*9 + t];
                if (v >= 0.f) bits |= (1u << i);
            }
            ((unsigned*)g_wcb)[j] = bits;
            int pc = __popc(bits);
            pc += __shfl_xor_sync(0xffffffffu, pc, 1);
            pc += __shfl_xor_sync(0xffffffffu, pc, 2);
            pc += __shfl_xor_sync(0xffffffffu, pc, 4);
            if (wd == 0) g_pwc[t*256 + o] = pc;
        }
    }
}

// ---------------------------------------------------------------------------
// Branch convs. Block = 32-px row strip, 512 thr.
// warpid: br = warpid & 3, q = warpid >> 2 (8-px quarter).
// Each lane computes oc = lane and oc+32 of its branch.
__global__ __launch_bounds__(512, 2) void branch_conv(
    const float* __restrict__ b1, const float* __restrict__ b2,
    const float* __restrict__ b3, const float* __restrict__ b4,
    const float* __restrict__ a1p)
{
    __shared__ uint4 xt[9*40*2];    // rows h-4..h+4, cols w0-4..w0+35
    const int bx = blockIdx.x, h = blockIdx.y, bb = blockIdx.z;
    const int w0 = bx*32;
    const int tid = threadIdx.x, lane = tid & 31;
    const int br = (tid >> 5) & 3, q = tid >> 7, px0 = q*8;

    for (int i = tid; i < 9*40; i += 512) {
        int r = i / 40, c = i % 40;
        int hh = h - 4 + r, ww = w0 - 4 + c;
        uint4 v0 = make_uint4(0,0,0,0), v1 = v0;
        if ((unsigned)hh < HH_ && (unsigned)ww < WW_) {
            const uint4* s = g_xbits + ((bb*HH_ + hh)*WW_ + ww)*2;
            v0 = s[0]; v1 = s[1];
        }
        xt[i*2] = v0; xt[i*2+1] = v1;
    }
    __syncthreads();

    const int sh = (br >= 2) ? ((br == 2) ? 1 : 2) : 0;
    const int sw = (br <  2) ? ((br == 0) ? 1 : 2) : 0;
    const bool edge = (br < 2) ? (bx == 0 || bx == 3) : (h < 4 || h > 123);

    int acc[16];                    // [0..7] oc=lane, [8..15] oc=lane+32
    #pragma unroll
    for (int p = 0; p < 16; p++) acc[p] = 0;

    #pragma unroll 1
    for (int k = 0; k < 5; k++) {
        const uint4* wpA = g_wb + ((br*5 + k)*64 + lane)*2;
        const uint4* wpB = wpA + 64;               // oc+32
        uint4 wA0 = wpA[0], wA1 = wpA[1];
        uint4 wB0 = wpB[0], wB1 = wpB[1];
        int d = k - 2;
        const uint4* s = xt + ((4 + d*sh)*40 + 4 + d*sw + px0)*2;
        #pragma unroll
        for (int p = 0; p < 8; p++) {
            uint4 x0 = s[2*p], x1 = s[2*p+1];
            cdot8_acc(acc[p],   x0, x1, wA0, wA1);
            cdot8_acc(acc[8+p], x0, x1, wB0, wB1);
        }
    }
    if (edge) {
        #pragma unroll 1
        for (int k = 0; k < 5; k++) {
            int pwA = 128 - g_pwb[(br*5 + k)*64 + lane];
            int pwB = 128 - g_pwb[(br*5 + k)*64 + lane + 32];
            int d = k - 2;
            bool hInv = ((unsigned)(h + d*sh) >= HH_);
            #pragma unroll
            for (int p = 0; p < 8; p++) {
                int ww = w0 + px0 + p + d*sw;
                if (hInv || (unsigned)ww >= WW_) {
                    acc[p]   += pwA;
                    acc[8+p] += pwB;
                }
            }
        }
    }

    const float* bp = (br==0) ? b1 : (br==1) ? b2 : (br==2) ? b3 : b4;
    const float biasA = bp[lane], biasB = bp[lane + 32];
    const float a1 = a1p[0];
    unsigned* mout = (unsigned*)g_mbits + ((bb*HH_ + h)*WW_ + w0 + px0)*8 + br*2;
    #pragma unroll
    for (int p = 0; p < 8; p++) {
        float vA = (float)(1280 - 2*acc[p])   + biasA;
        float vB = (float)(1280 - 2*acc[8+p]) + biasB;
        float pA = (vA >= 0.f) ? vA : a1*vA;
        float pB = (vB >= 0.f) ? vB : a1*vB;
        unsigned mA = __ballot_sync(0xffffffffu, pA >= 0.f);
        unsigned mB = __ballot_sync(0xffffffffu, pB >= 0.f);
        if (lane == 0) { mout[p*8] = mA; mout[p*8 + 1] = mB; }
    }
}

// ---------------------------------------------------------------------------
// Main 3x3 conv + bias + prelu + residual. Block = 32-px row strip, 512 thr.
// tid = half*256 + oc; thread owns 16 px of one oc. Rolling-column sweep:
// row-outer (3 taps' weights live), 18-column inner; each loaded column
// immediately feeds up to 3 pixel accumulators.
__global__ __launch_bounds__(512, 2) void main_conv(
    const float* __restrict__ x, const float* __restrict__ bc,
    const float* __restrict__ a2p, float* __restrict__ out)
{
    __shared__ uint4 xt[3*34*2];    // rows h-1..h+1, cols w0-1..w0+32
    const int bx = blockIdx.x, h = blockIdx.y, bb = blockIdx.z;
    const int w0 = bx*32;
    const int tid = threadIdx.x;
    const int oc = tid & 255, half = tid >> 8, px0 = half*16;

    for (int i = tid; i < 3*34; i += 512) {
        int r = i / 34, c = i % 34;
        int hh = h - 1 + r, ww = w0 - 1 + c;
        uint4 v0 = make_uint4(0,0,0,0), v1 = v0;
        if ((unsigned)hh < HH_ && (unsigned)ww < WW_) {
            const uint4* s = g_mbits + ((bb*HH_ + hh)*WW_ + ww)*2;
            v0 = s[0]; v1 = s[1];
        }
        xt[i*2] = v0; xt[i*2+1] = v1;
    }
    __syncthreads();

    int acc[16];
    #pragma unroll
    for (int p = 0; p < 16; p++) acc[p] = 0;

    #pragma unroll 1
    for (int r = 0; r < 3; r++) {
        const uint4* wp0 = g_wcb + ((r*3 + 0)*256 + oc)*2;
        const uint4* wp1 = g_wcb + ((r*3 + 1)*256 + oc)*2;
        const uint4* wp2 = g_wcb + ((r*3 + 2)*256 + oc)*2;
        uint4 w00 = wp0[0], w01 = wp0[1];
        uint4 w10 = wp1[0], w11 = wp1[1];
        uint4 w20 = wp2[0], w21 = wp2[1];
        const uint4* srow = xt + (r*34 + px0)*2;
        #pragma unroll
        for (int jj = 0; jj < 18; jj++) {
            uint4 x0 = srow[2*jj], x1 = srow[2*jj+1];
            if (jj >= 2)             cdot8_acc(acc[jj-2], x0, x1, w20, w21);
            if (jj >= 1 && jj <= 16) cdot8_acc(acc[jj-1], x0, x1, w10, w11);
            if (jj <= 15)            cdot8_acc(acc[jj],   x0, x1, w00, w01);
        }
    }
    const bool edge = (h == 0) | (h == 127) | (bx == 0) | (bx == 3);
    if (edge) {
        #pragma unroll 1
        for (int t = 0; t < 9; t++) {
            int pw = 128 - g_pwc[t*256 + oc];
            bool hInv = ((unsigned)(h + t/3 - 1) >= HH_);
            int dw = t%3 - 1;
            #pragma unroll
            for (int p = 0; p < 16; p++) {
                int ww = w0 + px0 + p + dw;
                if (hInv || (unsigned)ww >= WW_) acc[p] += pw;
            }
        }
    }

    const float a2 = a2p[0];
    const float bias = bc[oc];
    const size_t gbase = (((size_t)bb*CC_ + oc)*HH_ + h)*WW_ + w0 + px0;
    #pragma unroll
    for (int q = 0; q < 4; q++) {
        float4 xr = *(const float4*)(x + gbase + q*4);
        float4 o4;
        float v0 = (float)(2304 - 2*acc[q*4+0]) + bias; v0 = (v0 >= 0.f) ? v0 : a2*v0;
        float v1 = (float)(2304 - 2*acc[q*4+1]) + bias; v1 = (v1 >= 0.f) ? v1 : a2*v1;
        float v2 = (float)(2304 - 2*acc[q*4+2]) + bias; v2 = (v2 >= 0.f) ? v2 : a2*v2;
        float v3 = (float)(2304 - 2*acc[q*4+3]) + bias; v3 = (v3 >= 0.f) ? v3 : a2*v3;
        o4.x = v0 + xr.x; o4.y = v1 + xr.y; o4.z = v2 + xr.z; o4.w = v3 + xr.w;
        *(float4*)(out + gbase + q*4) = o4;
    }
}

// ---------------------------------------------------------------------------
extern "C" void kernel_launch(void* const* d_in, const int* in_sizes, int n_in,
                              void* d_out, int out_size) {
    const float* x  = (const float*)d_in[0];
    const float* w1 = (const float*)d_in[1];
    const float* b1 = (const float*)d_in[2];
    const float* w2 = (const float*)d_in[3];
    const float* b2 = (const float*)d_in[4];
    const float* w3 = (const float*)d_in[5];
    const float* b3 = (const float*)d_in[6];
    const float* w4 = (const float*)d_in[7];
    const float* b4 = (const float*)d_in[8];
    const float* a1 = (const float*)d_in[9];
    const float* wc = (const float*)d_in[10];
    const float* bc = (const float*)d_in[11];
    const float* a2 = (const float*)d_in[12];
    float* out = (float*)d_out;

    pack_x<<<4096, 256>>>(x);
    pack_w<<<112, 256>>>(w1, w2, w3, w4, wc);
    branch_conv<<<dim3(4,128,8), 512>>>(b1, b2, b3, b4, a1);
    main_conv<<<dim3(4,128,8), 512>>>(x, bc, a2, out);
}